// round 1
// baseline (speedup 1.0000x reference)
#include <cuda_runtime.h>

// 2-layer LSTM (H=8, IN=2) + FC(8->1), T=1024 sequential, B=16384 independent.
// Strategy: 8 lanes per batch element (lane j owns hidden unit j and the 4 gate
// rows g*8+j). All weights for a lane (112 floats) live in registers, loaded
// once. The T-loop is pure FFMA + MUFU + intra-warp shuffles (width-8 segments).

__device__ __forceinline__ float fast_ex2(float x) {
    float y; asm("ex2.approx.f32 %0, %1;" : "=f"(y) : "f"(x)); return y;
}
__device__ __forceinline__ float fast_rcp(float x) {
    float y; asm("rcp.approx.f32 %0, %1;" : "=f"(y) : "f"(x)); return y;
}
// sigmoid(x) = 1 / (1 + 2^(-x*log2(e)))
__device__ __forceinline__ float sigm(float x) {
    return fast_rcp(1.0f + fast_ex2(-1.4426950408889634f * x));
}
// tanh(x) = 2*sigmoid(2x) - 1
__device__ __forceinline__ float tanh_f(float x) {
    return fmaf(2.0f, fast_rcp(1.0f + fast_ex2(-2.8853900817779268f * x)), -1.0f);
}

__global__ void __launch_bounds__(128)
lstm2_fc_kernel(const float* __restrict__ x,
                const float* __restrict__ w_ih0, const float* __restrict__ w_hh0,
                const float* __restrict__ b_ih0, const float* __restrict__ b_hh0,
                const float* __restrict__ w_ih1, const float* __restrict__ w_hh1,
                const float* __restrict__ b_ih1, const float* __restrict__ b_hh1,
                const float* __restrict__ fc_w, const float* __restrict__ fc_b,
                float* __restrict__ out, int T, int B)
{
    int tid  = blockIdx.x * blockDim.x + threadIdx.x;
    int elem = tid >> 3;         // batch element
    int j    = tid & 7;          // hidden unit owned by this lane
    bool valid = (elem < B);
    if (elem >= B) elem = B - 1; // keep all lanes converged for shuffles

    // ---- Load per-lane weights into registers (once) ----
    // Gate order (PyTorch): i=0, f=1, g=2, o=3. Lane j handles rows g*8+j.
    float wi0[4][2], wh0[4][8], wi1[4][8], wh1[4][8], zb0[4], zb1[4];
#pragma unroll
    for (int g = 0; g < 4; g++) {
        int r = g * 8 + j;
        wi0[g][0] = __ldg(&w_ih0[r * 2 + 0]);
        wi0[g][1] = __ldg(&w_ih0[r * 2 + 1]);
#pragma unroll
        for (int k = 0; k < 8; k++) {
            wh0[g][k] = __ldg(&w_hh0[r * 8 + k]);
            wi1[g][k] = __ldg(&w_ih1[r * 8 + k]);
            wh1[g][k] = __ldg(&w_hh1[r * 8 + k]);
        }
        zb0[g] = __ldg(&b_ih0[r]) + __ldg(&b_hh0[r]);
        zb1[g] = __ldg(&b_ih1[r]) + __ldg(&b_hh1[r]);
    }

    // Replicated hidden state (every lane holds the full 8-vector) + own cell.
    float h0[8], h1[8];
    float c0 = 0.0f, c1 = 0.0f;
#pragma unroll
    for (int k = 0; k < 8; k++) { h0[k] = 0.0f; h1[k] = 0.0f; }

    const float2* xp = (const float2*)x;   // x: [T, B, 2] -> [T*B] float2
    float2 xv = __ldg(&xp[elem]);          // t = 0

    for (int t = 0; t < T; t++) {
        // Prefetch next timestep's input (clamped at the end).
        int tn = (t + 1 < T) ? (t + 1) : t;
        float2 xnext = __ldg(&xp[tn * B + elem]);

        // ---- Layer 0: z[g] = zb0 + Wih0 * x_t + Whh0 * h0 ----
        float z[4];
#pragma unroll
        for (int g = 0; g < 4; g++) {
            float acc = fmaf(wi0[g][0], xv.x, zb0[g]);
            acc = fmaf(wi0[g][1], xv.y, acc);
#pragma unroll
            for (int k = 0; k < 8; k++)
                acc = fmaf(wh0[g][k], h0[k], acc);
            z[g] = acc;
        }
        {
            float ig = sigm(z[0]);
            float fg = sigm(z[1]);
            float gg = tanh_f(z[2]);
            float og = sigm(z[3]);
            c0 = fmaf(fg, c0, ig * gg);
            float h0j = og * tanh_f(c0);
#pragma unroll
            for (int k = 0; k < 8; k++)
                h0[k] = __shfl_sync(0xffffffffu, h0j, k, 8);
        }

        // ---- Layer 1: z[g] = zb1 + Wih1 * h0_new + Whh1 * h1 ----
#pragma unroll
        for (int g = 0; g < 4; g++) {
            float acc = zb1[g];
#pragma unroll
            for (int k = 0; k < 8; k++) {
                acc = fmaf(wi1[g][k], h0[k], acc);
                acc = fmaf(wh1[g][k], h1[k], acc);
            }
            z[g] = acc;
        }
        {
            float ig = sigm(z[0]);
            float fg = sigm(z[1]);
            float gg = tanh_f(z[2]);
            float og = sigm(z[3]);
            c1 = fmaf(fg, c1, ig * gg);
            float h1j = og * tanh_f(c1);
#pragma unroll
            for (int k = 0; k < 8; k++)
                h1[k] = __shfl_sync(0xffffffffu, h1j, k, 8);
        }

        xv = xnext;
    }

    // ---- FC: out[b] = fc_w . h1_last + fc_b (lane j==0 writes) ----
    if (valid && j == 0) {
        float acc = __ldg(&fc_b[0]);
#pragma unroll
        for (int k = 0; k < 8; k++)
            acc = fmaf(__ldg(&fc_w[k]), h1[k], acc);
        out[elem] = acc;
    }
}

extern "C" void kernel_launch(void* const* d_in, const int* in_sizes, int n_in,
                              void* d_out, int out_size)
{
    const float* x      = (const float*)d_in[0];
    const float* w_ih0  = (const float*)d_in[1];
    const float* w_hh0  = (const float*)d_in[2];
    const float* b_ih0  = (const float*)d_in[3];
    const float* b_hh0  = (const float*)d_in[4];
    const float* w_ih1  = (const float*)d_in[5];
    const float* w_hh1  = (const float*)d_in[6];
    const float* b_ih1  = (const float*)d_in[7];
    const float* b_hh1  = (const float*)d_in[8];
    const float* fc_w   = (const float*)d_in[9];
    const float* fc_b   = (const float*)d_in[10];
    float* out = (float*)d_out;

    int B = out_size;                     // [B, 1] output
    int T = in_sizes[0] / (2 * B);        // x: [T, B, 2]

    int threads = 128;
    int total   = B * 8;                  // 8 lanes per element
    int blocks  = (total + threads - 1) / threads;
    lstm2_fc_kernel<<<blocks, threads>>>(x, w_ih0, w_hh0, b_ih0, b_hh0,
                                         w_ih1, w_hh1, b_ih1, b_hh1,
                                         fc_w, fc_b, out, T, B);
}

// round 2
// speedup vs baseline: 1.0423x; 1.0423x over previous
#include <cuda_runtime.h>

// 2-layer LSTM (H=8, IN=2) + FC(8->1), T=1024, B=16384.
// 8 lanes per batch element (lane j owns hidden unit j, gate rows g*8+j),
// and each thread processes TWO adjacent batch elements (shared weight regs,
// 2 independent dependency chains per thread for latency hiding).

__device__ __forceinline__ float fast_ex2(float x) {
    float y; asm("ex2.approx.f32 %0, %1;" : "=f"(y) : "f"(x)); return y;
}
__device__ __forceinline__ float fast_rcp(float x) {
    float y; asm("rcp.approx.f32 %0, %1;" : "=f"(y) : "f"(x)); return y;
}
// sigmoid(x) = 1/(1 + 2^(-x*log2 e))
__device__ __forceinline__ float sigm(float x) {
    return fast_rcp(1.0f + fast_ex2(-1.4426950408889634f * x));
}
// tanh(x) = 2*sigmoid(2x) - 1
__device__ __forceinline__ float tanh_f(float x) {
    return fmaf(2.0f, fast_rcp(1.0f + fast_ex2(-2.8853900817779268f * x)), -1.0f);
}

__global__ void __launch_bounds__(64)
lstm2_fc_kernel(const float* __restrict__ x,
                const float* __restrict__ w_ih0, const float* __restrict__ w_hh0,
                const float* __restrict__ b_ih0, const float* __restrict__ b_hh0,
                const float* __restrict__ w_ih1, const float* __restrict__ w_hh1,
                const float* __restrict__ b_ih1, const float* __restrict__ b_hh1,
                const float* __restrict__ fc_w, const float* __restrict__ fc_b,
                float* __restrict__ out, int T, int B)
{
    int tid   = blockIdx.x * blockDim.x + threadIdx.x;
    int q     = tid >> 3;          // element-pair index: elements 2q, 2q+1
    int j     = tid & 7;           // hidden unit owned by this lane
    int halfB = B >> 1;
    bool valid = (q < halfB);
    if (!valid) q = halfB - 1;     // keep lanes converged for shuffles

    // ---- Per-lane weights in registers (loaded once, shared by both elems) ----
    float wi0[4][2], wh0[4][8], wi1[4][8], wh1[4][8], zb0[4], zb1[4];
#pragma unroll
    for (int g = 0; g < 4; g++) {
        int r = g * 8 + j;
        wi0[g][0] = __ldg(&w_ih0[r * 2 + 0]);
        wi0[g][1] = __ldg(&w_ih0[r * 2 + 1]);
#pragma unroll
        for (int k = 0; k < 8; k++) {
            wh0[g][k] = __ldg(&w_hh0[r * 8 + k]);
            wi1[g][k] = __ldg(&w_ih1[r * 8 + k]);
            wh1[g][k] = __ldg(&w_hh1[r * 8 + k]);
        }
        zb0[g] = __ldg(&b_ih0[r]) + __ldg(&b_hh0[r]);
        zb1[g] = __ldg(&b_ih1[r]) + __ldg(&b_hh1[r]);
    }

    // ---- State: 2 elements, replicated h vectors + own cell ----
    float h0[2][8], h1[2][8], c0[2], c1[2];
#pragma unroll
    for (int p = 0; p < 2; p++) {
        c0[p] = 0.0f; c1[p] = 0.0f;
#pragma unroll
        for (int k = 0; k < 8; k++) { h0[p][k] = 0.0f; h1[p][k] = 0.0f; }
    }

    // x: [T, B, 2] floats; elements 2q,2q+1 at step t form one float4.
    const float4* xp = (const float4*)x;
    float4 xv = __ldg(&xp[q]);     // t = 0

    for (int t = 0; t < T; t++) {
        // Prefetch next step's inputs.
        long nidx = (long)((t + 1 < T) ? (t + 1) : t) * halfB + q;
        float4 xnext = __ldg(&xp[nidx]);

        float xin[2][2];
        xin[0][0] = xv.x; xin[0][1] = xv.y;
        xin[1][0] = xv.z; xin[1][1] = xv.w;

        // ---- Layer 0 ----
        float z[2][4];
#pragma unroll
        for (int g = 0; g < 4; g++) {
#pragma unroll
            for (int p = 0; p < 2; p++) {
                float acc = fmaf(wi0[g][0], xin[p][0], zb0[g]);
                acc = fmaf(wi0[g][1], xin[p][1], acc);
#pragma unroll
                for (int k = 0; k < 8; k++)
                    acc = fmaf(wh0[g][k], h0[p][k], acc);
                z[p][g] = acc;
            }
        }
        {
            float h0j[2];
#pragma unroll
            for (int p = 0; p < 2; p++) {
                float ig = sigm(z[p][0]);
                float fg = sigm(z[p][1]);
                float gg = tanh_f(z[p][2]);
                float og = sigm(z[p][3]);
                c0[p] = fmaf(fg, c0[p], ig * gg);
                h0j[p] = og * tanh_f(c0[p]);
            }
#pragma unroll
            for (int k = 0; k < 8; k++) {
                h0[0][k] = __shfl_sync(0xffffffffu, h0j[0], k, 8);
                h0[1][k] = __shfl_sync(0xffffffffu, h0j[1], k, 8);
            }
        }

        // ---- Layer 1 ----
#pragma unroll
        for (int g = 0; g < 4; g++) {
#pragma unroll
            for (int p = 0; p < 2; p++) {
                float acc = zb1[g];
#pragma unroll
                for (int k = 0; k < 8; k++) {
                    acc = fmaf(wi1[g][k], h0[p][k], acc);
                    acc = fmaf(wh1[g][k], h1[p][k], acc);
                }
                z[p][g] = acc;
            }
        }
        {
            float h1j[2];
#pragma unroll
            for (int p = 0; p < 2; p++) {
                float ig = sigm(z[p][0]);
                float fg = sigm(z[p][1]);
                float gg = tanh_f(z[p][2]);
                float og = sigm(z[p][3]);
                c1[p] = fmaf(fg, c1[p], ig * gg);
                h1j[p] = og * tanh_f(c1[p]);
            }
#pragma unroll
            for (int k = 0; k < 8; k++) {
                h1[0][k] = __shfl_sync(0xffffffffu, h1j[0], k, 8);
                h1[1][k] = __shfl_sync(0xffffffffu, h1j[1], k, 8);
            }
        }

        xv = xnext;
    }

    // ---- FC: out[b] = fc_w . h1_last + fc_b (lane j==0 writes both) ----
    if (valid && j == 0) {
        float fw[8];
#pragma unroll
        for (int k = 0; k < 8; k++) fw[k] = __ldg(&fc_w[k]);
        float fb = __ldg(&fc_b[0]);
#pragma unroll
        for (int p = 0; p < 2; p++) {
            float acc = fb;
#pragma unroll
            for (int k = 0; k < 8; k++)
                acc = fmaf(fw[k], h1[p][k], acc);
            out[2 * q + p] = acc;
        }
    }
}

extern "C" void kernel_launch(void* const* d_in, const int* in_sizes, int n_in,
                              void* d_out, int out_size)
{
    const float* x      = (const float*)d_in[0];
    const float* w_ih0  = (const float*)d_in[1];
    const float* w_hh0  = (const float*)d_in[2];
    const float* b_ih0  = (const float*)d_in[3];
    const float* b_hh0  = (const float*)d_in[4];
    const float* w_ih1  = (const float*)d_in[5];
    const float* w_hh1  = (const float*)d_in[6];
    const float* b_ih1  = (const float*)d_in[7];
    const float* b_hh1  = (const float*)d_in[8];
    const float* fc_w   = (const float*)d_in[9];
    const float* fc_b   = (const float*)d_in[10];
    float* out = (float*)d_out;

    int B = out_size;                 // [B, 1]
    int T = in_sizes[0] / (2 * B);    // x: [T, B, 2]

    int threads = 64;
    int total   = (B / 2) * 8;        // 8 lanes per element pair
    int blocks  = (total + threads - 1) / threads;
    lstm2_fc_kernel<<<blocks, threads>>>(x, w_ih0, w_hh0, b_ih0, b_hh0,
                                         w_ih1, w_hh1, b_ih1, b_hh1,
                                         fc_w, fc_b, out, T, B);
}

// round 3
// speedup vs baseline: 1.0900x; 1.0458x over previous
#include <cuda_runtime.h>

// 2-layer LSTM (H=8, IN=2) + FC(8->1), T=1024, B=16384.
// 8 lanes per batch element (lane j owns hidden unit j, gate rows g*8+j),
// 2 batch elements per thread (shared weights, 2 independent chains),
// and all matvec FMAs packed 2-wide via fma.rn.f32x2 (FFMA2) across k.

using u64 = unsigned long long;

__device__ __forceinline__ u64 pack2(float lo, float hi) {
    u64 r; asm("mov.b64 %0, {%1, %2};" : "=l"(r) : "f"(lo), "f"(hi)); return r;
}
__device__ __forceinline__ float2 unpack2(u64 v) {
    float2 f; asm("mov.b64 {%0, %1}, %2;" : "=f"(f.x), "=f"(f.y) : "l"(v)); return f;
}
__device__ __forceinline__ u64 ffma2(u64 a, u64 b, u64 c) {
    u64 d; asm("fma.rn.f32x2 %0, %1, %2, %3;" : "=l"(d) : "l"(a), "l"(b), "l"(c)); return d;
}

__device__ __forceinline__ float fast_ex2(float x) {
    float y; asm("ex2.approx.f32 %0, %1;" : "=f"(y) : "f"(x)); return y;
}
__device__ __forceinline__ float fast_rcp(float x) {
    float y; asm("rcp.approx.f32 %0, %1;" : "=f"(y) : "f"(x)); return y;
}
// sigmoid(x) = 1/(1 + 2^(-x*log2 e))
__device__ __forceinline__ float sigm(float x) {
    return fast_rcp(1.0f + fast_ex2(-1.4426950408889634f * x));
}
// tanh(x) = 2*sigmoid(2x) - 1
__device__ __forceinline__ float tanh_f(float x) {
    return fmaf(2.0f, fast_rcp(1.0f + fast_ex2(-2.8853900817779268f * x)), -1.0f);
}

__global__ void __launch_bounds__(64)
lstm2_fc_kernel(const float* __restrict__ x,
                const float* __restrict__ w_ih0, const float* __restrict__ w_hh0,
                const float* __restrict__ b_ih0, const float* __restrict__ b_hh0,
                const float* __restrict__ w_ih1, const float* __restrict__ w_hh1,
                const float* __restrict__ b_ih1, const float* __restrict__ b_hh1,
                const float* __restrict__ fc_w, const float* __restrict__ fc_b,
                float* __restrict__ out, int T, int B)
{
    int tid   = blockIdx.x * blockDim.x + threadIdx.x;
    int q     = tid >> 3;          // element-pair index: elements 2q, 2q+1
    int j     = tid & 7;           // hidden unit owned by this lane
    int halfB = B >> 1;
    bool valid = (q < halfB);
    if (!valid) q = halfB - 1;     // keep lanes converged for shuffles

    // ---- Per-lane weights, packed in pairs across k (loaded once) ----
    u64 wi0p[4], wh0p[4][4], wi1p[4][4], wh1p[4][4], zb0p[4], zb1p[4];
#pragma unroll
    for (int g = 0; g < 4; g++) {
        int r = g * 8 + j;
        wi0p[g] = pack2(__ldg(&w_ih0[r * 2 + 0]), __ldg(&w_ih0[r * 2 + 1]));
#pragma unroll
        for (int m = 0; m < 4; m++) {
            wh0p[g][m] = pack2(__ldg(&w_hh0[r * 8 + 2 * m]), __ldg(&w_hh0[r * 8 + 2 * m + 1]));
            wi1p[g][m] = pack2(__ldg(&w_ih1[r * 8 + 2 * m]), __ldg(&w_ih1[r * 8 + 2 * m + 1]));
            wh1p[g][m] = pack2(__ldg(&w_hh1[r * 8 + 2 * m]), __ldg(&w_hh1[r * 8 + 2 * m + 1]));
        }
        float zb0 = __ldg(&b_ih0[r]) + __ldg(&b_hh0[r]);
        float zb1 = __ldg(&b_ih1[r]) + __ldg(&b_hh1[r]);
        zb0p[g] = pack2(zb0, 0.0f);
        zb1p[g] = pack2(zb1, 0.0f);
    }

    // ---- State: 2 elements; h vectors stored as 4 packed pairs each ----
    u64 h0p[2][4], h1p[2][4];
    float c0[2], c1[2];
    u64 zero2 = pack2(0.0f, 0.0f);
#pragma unroll
    for (int p = 0; p < 2; p++) {
        c0[p] = 0.0f; c1[p] = 0.0f;
#pragma unroll
        for (int m = 0; m < 4; m++) { h0p[p][m] = zero2; h1p[p][m] = zero2; }
    }

    // x: [T, B, 2]; elements 2q,2q+1 at step t = one 16B load = 2 packed pairs.
    const ulonglong2* xp = (const ulonglong2*)x;
    ulonglong2 xv = __ldg(&xp[q]);   // t = 0

    for (int t = 0; t < T; t++) {
        long nidx = (long)((t + 1 < T) ? (t + 1) : t) * halfB + q;
        ulonglong2 xnext = __ldg(&xp[nidx]);

        u64 xq[2] = { xv.x, xv.y };

        // ---- Layer 0 ----
#pragma unroll
        for (int p = 0; p < 2; p++) {
            float z[4];
#pragma unroll
            for (int g = 0; g < 4; g++) {
                u64 acc = ffma2(wi0p[g], xq[p], zb0p[g]);
#pragma unroll
                for (int m = 0; m < 4; m++)
                    acc = ffma2(wh0p[g][m], h0p[p][m], acc);
                float2 u = unpack2(acc);
                z[g] = u.x + u.y;
            }
            float ig = sigm(z[0]);
            float fg = sigm(z[1]);
            float gg = tanh_f(z[2]);
            float og = sigm(z[3]);
            c0[p] = fmaf(fg, c0[p], ig * gg);
            float h0j = og * tanh_f(c0[p]);
#pragma unroll
            for (int m = 0; m < 4; m++)
                h0p[p][m] = pack2(__shfl_sync(0xffffffffu, h0j, 2 * m,     8),
                                  __shfl_sync(0xffffffffu, h0j, 2 * m + 1, 8));
        }

        // ---- Layer 1 ----
#pragma unroll
        for (int p = 0; p < 2; p++) {
            float z[4];
#pragma unroll
            for (int g = 0; g < 4; g++) {
                u64 acc = ffma2(wi1p[g][0], h0p[p][0], zb1p[g]);
#pragma unroll
                for (int m = 1; m < 4; m++)
                    acc = ffma2(wi1p[g][m], h0p[p][m], acc);
#pragma unroll
                for (int m = 0; m < 4; m++)
                    acc = ffma2(wh1p[g][m], h1p[p][m], acc);
                float2 u = unpack2(acc);
                z[g] = u.x + u.y;
            }
            float ig = sigm(z[0]);
            float fg = sigm(z[1]);
            float gg = tanh_f(z[2]);
            float og = sigm(z[3]);
            c1[p] = fmaf(fg, c1[p], ig * gg);
            float h1j = og * tanh_f(c1[p]);
#pragma unroll
            for (int m = 0; m < 4; m++)
                h1p[p][m] = pack2(__shfl_sync(0xffffffffu, h1j, 2 * m,     8),
                                  __shfl_sync(0xffffffffu, h1j, 2 * m + 1, 8));
        }

        xv = xnext;
    }

    // ---- FC: out[b] = fc_w . h1_last + fc_b (lane j==0 writes both) ----
    if (valid && j == 0) {
        float fw[8];
#pragma unroll
        for (int k = 0; k < 8; k++) fw[k] = __ldg(&fc_w[k]);
        float fb = __ldg(&fc_b[0]);
#pragma unroll
        for (int p = 0; p < 2; p++) {
            float acc = fb;
#pragma unroll
            for (int m = 0; m < 4; m++) {
                float2 u = unpack2(h1p[p][m]);
                acc = fmaf(fw[2 * m], u.x, acc);
                acc = fmaf(fw[2 * m + 1], u.y, acc);
            }
            out[2 * q + p] = acc;
        }
    }
}

extern "C" void kernel_launch(void* const* d_in, const int* in_sizes, int n_in,
                              void* d_out, int out_size)
{
    const float* x      = (const float*)d_in[0];
    const float* w_ih0  = (const float*)d_in[1];
    const float* w_hh0  = (const float*)d_in[2];
    const float* b_ih0  = (const float*)d_in[3];
    const float* b_hh0  = (const float*)d_in[4];
    const float* w_ih1  = (const float*)d_in[5];
    const float* w_hh1  = (const float*)d_in[6];
    const float* b_ih1  = (const float*)d_in[7];
    const float* b_hh1  = (const float*)d_in[8];
    const float* fc_w   = (const float*)d_in[9];
    const float* fc_b   = (const float*)d_in[10];
    float* out = (float*)d_out;

    int B = out_size;                 // [B, 1]
    int T = in_sizes[0] / (2 * B);    // x: [T, B, 2]

    int threads = 64;
    int total   = (B / 2) * 8;        // 8 lanes per element pair
    int blocks  = (total + threads - 1) / threads;
    lstm2_fc_kernel<<<blocks, threads>>>(x, w_ih0, w_hh0, b_ih0, b_hh0,
                                         w_ih1, w_hh1, b_ih1, b_hh1,
                                         fc_w, fc_b, out, T, B);
}

// round 4
// speedup vs baseline: 1.3174x; 1.2086x over previous
#include <cuda_runtime.h>

// 2-layer LSTM (H=8, IN=2) + FC(8->1), T=1024, B=16384.
// 8 lanes per batch element (lane j owns hidden unit j, gate rows g*8+j),
// FOUR batch elements per thread (shared weight regs, 4 independent
// dependency chains per thread), matvecs packed 2-wide via fma.rn.f32x2.

using u64 = unsigned long long;

__device__ __forceinline__ u64 pack2(float lo, float hi) {
    u64 r; asm("mov.b64 %0, {%1, %2};" : "=l"(r) : "f"(lo), "f"(hi)); return r;
}
__device__ __forceinline__ float2 unpack2(u64 v) {
    float2 f; asm("mov.b64 {%0, %1}, %2;" : "=f"(f.x), "=f"(f.y) : "l"(v)); return f;
}
__device__ __forceinline__ u64 ffma2(u64 a, u64 b, u64 c) {
    u64 d; asm("fma.rn.f32x2 %0, %1, %2, %3;" : "=l"(d) : "l"(a), "l"(b), "l"(c)); return d;
}

__device__ __forceinline__ float fast_ex2(float x) {
    float y; asm("ex2.approx.f32 %0, %1;" : "=f"(y) : "f"(x)); return y;
}
__device__ __forceinline__ float fast_rcp(float x) {
    float y; asm("rcp.approx.f32 %0, %1;" : "=f"(y) : "f"(x)); return y;
}
// sigmoid(x) = 1/(1 + 2^(-x*log2 e))
__device__ __forceinline__ float sigm(float x) {
    return fast_rcp(1.0f + fast_ex2(-1.4426950408889634f * x));
}
// tanh(x) = 2*sigmoid(2x) - 1
__device__ __forceinline__ float tanh_f(float x) {
    return fmaf(2.0f, fast_rcp(1.0f + fast_ex2(-2.8853900817779268f * x)), -1.0f);
}

__global__ void __launch_bounds__(64)
lstm2_fc_kernel(const float* __restrict__ x,
                const float* __restrict__ w_ih0, const float* __restrict__ w_hh0,
                const float* __restrict__ b_ih0, const float* __restrict__ b_hh0,
                const float* __restrict__ w_ih1, const float* __restrict__ w_hh1,
                const float* __restrict__ b_ih1, const float* __restrict__ b_hh1,
                const float* __restrict__ fc_w, const float* __restrict__ fc_b,
                float* __restrict__ out, int T, int B)
{
    int tid   = blockIdx.x * blockDim.x + threadIdx.x;
    int q     = tid >> 3;          // quad index: elements 4q .. 4q+3
    int j     = tid & 7;           // hidden unit owned by this lane
    int quadB = B >> 2;
    bool valid = (q < quadB);
    if (!valid) q = quadB - 1;     // keep lanes converged for shuffles

    // ---- Per-lane weights, packed in pairs across k (loaded once) ----
    u64 wi0p[4], wh0p[4][4], wi1p[4][4], wh1p[4][4], zb0p[4], zb1p[4];
#pragma unroll
    for (int g = 0; g < 4; g++) {
        int r = g * 8 + j;
        wi0p[g] = pack2(__ldg(&w_ih0[r * 2 + 0]), __ldg(&w_ih0[r * 2 + 1]));
#pragma unroll
        for (int m = 0; m < 4; m++) {
            wh0p[g][m] = pack2(__ldg(&w_hh0[r * 8 + 2 * m]), __ldg(&w_hh0[r * 8 + 2 * m + 1]));
            wi1p[g][m] = pack2(__ldg(&w_ih1[r * 8 + 2 * m]), __ldg(&w_ih1[r * 8 + 2 * m + 1]));
            wh1p[g][m] = pack2(__ldg(&w_hh1[r * 8 + 2 * m]), __ldg(&w_hh1[r * 8 + 2 * m + 1]));
        }
        float zb0 = __ldg(&b_ih0[r]) + __ldg(&b_hh0[r]);
        float zb1 = __ldg(&b_ih1[r]) + __ldg(&b_hh1[r]);
        zb0p[g] = pack2(zb0, 0.0f);
        zb1p[g] = pack2(zb1, 0.0f);
    }

    // ---- State: 4 elements; h vectors stored as 4 packed pairs each ----
    u64 h0p[4][4], h1p[4][4];
    float c0[4], c1[4];
    u64 zero2 = pack2(0.0f, 0.0f);
#pragma unroll
    for (int p = 0; p < 4; p++) {
        c0[p] = 0.0f; c1[p] = 0.0f;
#pragma unroll
        for (int m = 0; m < 4; m++) { h0p[p][m] = zero2; h1p[p][m] = zero2; }
    }

    // x: [T, B, 2] floats. Elements 4q..4q+3 at step t = 32 bytes =
    // two ulonglong2 loads. Pointer-stepped addressing (no per-step IMAD).
    int strideT = B >> 1;                       // ulonglong2 per timestep row
    const ulonglong2* xp = (const ulonglong2*)x + 2 * q;
    ulonglong2 xa = __ldg(xp);                  // t = 0, elems 4q,4q+1
    ulonglong2 xb = __ldg(xp + 1);              //        elems 4q+2,4q+3

#pragma unroll 1
    for (int t = 0; t < T; t++) {
        // Prefetch next timestep (clamped on last iteration).
        const ulonglong2* xn = xp + ((t + 1 < T) ? strideT : 0);
        ulonglong2 na = __ldg(xn);
        ulonglong2 nb = __ldg(xn + 1);

        u64 xq[4] = { xa.x, xa.y, xb.x, xb.y };

        // ---- Layer 0 ----
#pragma unroll
        for (int p = 0; p < 4; p++) {
            float z[4];
#pragma unroll
            for (int g = 0; g < 4; g++) {
                u64 acc = ffma2(wi0p[g], xq[p], zb0p[g]);
#pragma unroll
                for (int m = 0; m < 4; m++)
                    acc = ffma2(wh0p[g][m], h0p[p][m], acc);
                float2 u = unpack2(acc);
                z[g] = u.x + u.y;
            }
            float ig = sigm(z[0]);
            float fg = sigm(z[1]);
            float gg = tanh_f(z[2]);
            float og = sigm(z[3]);
            c0[p] = fmaf(fg, c0[p], ig * gg);
            float h0j = og * tanh_f(c0[p]);
#pragma unroll
            for (int m = 0; m < 4; m++)
                h0p[p][m] = pack2(__shfl_sync(0xffffffffu, h0j, 2 * m,     8),
                                  __shfl_sync(0xffffffffu, h0j, 2 * m + 1, 8));
        }

        // ---- Layer 1 ----
#pragma unroll
        for (int p = 0; p < 4; p++) {
            float z[4];
#pragma unroll
            for (int g = 0; g < 4; g++) {
                u64 acc = ffma2(wi1p[g][0], h0p[p][0], zb1p[g]);
#pragma unroll
                for (int m = 1; m < 4; m++)
                    acc = ffma2(wi1p[g][m], h0p[p][m], acc);
#pragma unroll
                for (int m = 0; m < 4; m++)
                    acc = ffma2(wh1p[g][m], h1p[p][m], acc);
                float2 u = unpack2(acc);
                z[g] = u.x + u.y;
            }
            float ig = sigm(z[0]);
            float fg = sigm(z[1]);
            float gg = tanh_f(z[2]);
            float og = sigm(z[3]);
            c1[p] = fmaf(fg, c1[p], ig * gg);
            float h1j = og * tanh_f(c1[p]);
#pragma unroll
            for (int m = 0; m < 4; m++)
                h1p[p][m] = pack2(__shfl_sync(0xffffffffu, h1j, 2 * m,     8),
                                  __shfl_sync(0xffffffffu, h1j, 2 * m + 1, 8));
        }

        xa = na; xb = nb; xp = xn;
    }

    // ---- FC: out[b] = fc_w . h1_last + fc_b (lane j==0 writes 4) ----
    if (valid && j == 0) {
        float fw[8];
#pragma unroll
        for (int k = 0; k < 8; k++) fw[k] = __ldg(&fc_w[k]);
        float fb = __ldg(&fc_b[0]);
        float4 o;
        float* op = &o.x;
#pragma unroll
        for (int p = 0; p < 4; p++) {
            float acc = fb;
#pragma unroll
            for (int m = 0; m < 4; m++) {
                float2 u = unpack2(h1p[p][m]);
                acc = fmaf(fw[2 * m], u.x, acc);
                acc = fmaf(fw[2 * m + 1], u.y, acc);
            }
            op[p] = acc;
        }
        *(float4*)&out[4 * q] = o;
    }
}

extern "C" void kernel_launch(void* const* d_in, const int* in_sizes, int n_in,
                              void* d_out, int out_size)
{
    const float* x      = (const float*)d_in[0];
    const float* w_ih0  = (const float*)d_in[1];
    const float* w_hh0  = (const float*)d_in[2];
    const float* b_ih0  = (const float*)d_in[3];
    const float* b_hh0  = (const float*)d_in[4];
    const float* w_ih1  = (const float*)d_in[5];
    const float* w_hh1  = (const float*)d_in[6];
    const float* b_ih1  = (const float*)d_in[7];
    const float* b_hh1  = (const float*)d_in[8];
    const float* fc_w   = (const float*)d_in[9];
    const float* fc_b   = (const float*)d_in[10];
    float* out = (float*)d_out;

    int B = out_size;                 // [B, 1]
    int T = in_sizes[0] / (2 * B);    // x: [T, B, 2]

    int threads = 64;
    int total   = (B / 4) * 8;        // 8 lanes per element quad
    int blocks  = (total + threads - 1) / threads;
    lstm2_fc_kernel<<<blocks, threads>>>(x, w_ih0, w_hh0, b_ih0, b_hh0,
                                         w_ih1, w_hh1, b_ih1, b_hh1,
                                         fc_w, fc_b, out, T, B);
}

// round 5
// speedup vs baseline: 1.3297x; 1.0093x over previous
#include <cuda_runtime.h>

// 2-layer LSTM (H=8, IN=2) + FC(8->1), T=1024, B=16384.
// 8 lanes per batch element (lane j owns hidden unit j, gate rows g*8+j),
// 4 batch elements per thread, matvecs packed 2-wide via fma.rn.f32x2,
// h broadcast via shared memory (STS.32 + LDS.128) instead of shuffles.
// 32-thread blocks for fine-grained SM load balance.

using u64 = unsigned long long;

__device__ __forceinline__ u64 pack2(float lo, float hi) {
    u64 r; asm("mov.b64 %0, {%1, %2};" : "=l"(r) : "f"(lo), "f"(hi)); return r;
}
__device__ __forceinline__ float2 unpack2(u64 v) {
    float2 f; asm("mov.b64 {%0, %1}, %2;" : "=f"(f.x), "=f"(f.y) : "l"(v)); return f;
}
__device__ __forceinline__ u64 ffma2(u64 a, u64 b, u64 c) {
    u64 d; asm("fma.rn.f32x2 %0, %1, %2, %3;" : "=l"(d) : "l"(a), "l"(b), "l"(c)); return d;
}

__device__ __forceinline__ float fast_ex2(float x) {
    float y; asm("ex2.approx.f32 %0, %1;" : "=f"(y) : "f"(x)); return y;
}
__device__ __forceinline__ float fast_rcp(float x) {
    float y; asm("rcp.approx.f32 %0, %1;" : "=f"(y) : "f"(x)); return y;
}
// sigmoid(x) = 1/(1 + 2^(-x*log2 e))
__device__ __forceinline__ float sigm(float x) {
    return fast_rcp(1.0f + fast_ex2(-1.4426950408889634f * x));
}
// tanh(x) = 2*sigmoid(2x) - 1
__device__ __forceinline__ float tanh_f(float x) {
    return fmaf(2.0f, fast_rcp(1.0f + fast_ex2(-2.8853900817779268f * x)), -1.0f);
}

__global__ void __launch_bounds__(32)
lstm2_fc_kernel(const float* __restrict__ x,
                const float* __restrict__ w_ih0, const float* __restrict__ w_hh0,
                const float* __restrict__ b_ih0, const float* __restrict__ b_hh0,
                const float* __restrict__ w_ih1, const float* __restrict__ w_hh1,
                const float* __restrict__ b_ih1, const float* __restrict__ b_hh1,
                const float* __restrict__ fc_w, const float* __restrict__ fc_b,
                float* __restrict__ out, int T, int B)
{
    // Broadcast buffers: [elem p][quad-in-warp][hidden j]. Store side:
    // 32 lanes hit 32 consecutive words (conflict-free). Load side: 8 lanes
    // per quad read the same 16B (broadcast), 4 quads span one 128B line.
    __shared__ alignas(16) float h0s[4][4][8];
    __shared__ alignas(16) float h1s[4][4][8];

    int lane  = threadIdx.x;       // 32-thread blocks: lane == tid in block
    int ql    = lane >> 3;         // quad slot within this warp (0..3)
    int j     = lane & 7;          // hidden unit owned by this lane
    int tid   = blockIdx.x * 32 + lane;
    int q     = tid >> 3;          // global quad index: elements 4q..4q+3
    int quadB = B >> 2;
    bool valid = (q < quadB);
    if (!valid) q = quadB - 1;

    // ---- Per-lane weights, packed in pairs across k (loaded once) ----
    u64 wi0p[4], wh0p[4][4], wi1p[4][4], wh1p[4][4], zb0p[4], zb1p[4];
#pragma unroll
    for (int g = 0; g < 4; g++) {
        int r = g * 8 + j;
        wi0p[g] = pack2(__ldg(&w_ih0[r * 2 + 0]), __ldg(&w_ih0[r * 2 + 1]));
#pragma unroll
        for (int m = 0; m < 4; m++) {
            wh0p[g][m] = pack2(__ldg(&w_hh0[r * 8 + 2 * m]), __ldg(&w_hh0[r * 8 + 2 * m + 1]));
            wi1p[g][m] = pack2(__ldg(&w_ih1[r * 8 + 2 * m]), __ldg(&w_ih1[r * 8 + 2 * m + 1]));
            wh1p[g][m] = pack2(__ldg(&w_hh1[r * 8 + 2 * m]), __ldg(&w_hh1[r * 8 + 2 * m + 1]));
        }
        float zb0 = __ldg(&b_ih0[r]) + __ldg(&b_hh0[r]);
        float zb1 = __ldg(&b_ih1[r]) + __ldg(&b_hh1[r]);
        zb0p[g] = pack2(zb0, 0.0f);
        zb1p[g] = pack2(zb1, 0.0f);
    }

    // ---- State: 4 elements; replicated h as packed pairs + own cells ----
    u64 h0p[4][4], h1p[4][4];
    float c0[4], c1[4];
    u64 zero2 = pack2(0.0f, 0.0f);
#pragma unroll
    for (int p = 0; p < 4; p++) {
        c0[p] = 0.0f; c1[p] = 0.0f;
#pragma unroll
        for (int m = 0; m < 4; m++) { h0p[p][m] = zero2; h1p[p][m] = zero2; }
    }

    // x: [T, B, 2] floats; elements 4q..4q+3 = 32B = two 16B loads.
    int strideT = B >> 1;                       // ulonglong2 per timestep row
    const ulonglong2* xp = (const ulonglong2*)x + 2 * q;
    ulonglong2 xa = __ldg(xp);
    ulonglong2 xb = __ldg(xp + 1);

#pragma unroll 1
    for (int t = 0; t < T; t++) {
        const ulonglong2* xn = xp + ((t + 1 < T) ? strideT : 0);
        ulonglong2 na = __ldg(xn);
        ulonglong2 nb = __ldg(xn + 1);

        u64 xq[4] = { xa.x, xa.y, xb.x, xb.y };

        // ---- Layer 0: compute own h0[j] for each element, publish ----
#pragma unroll
        for (int p = 0; p < 4; p++) {
            float z[4];
#pragma unroll
            for (int g = 0; g < 4; g++) {
                u64 acc = ffma2(wi0p[g], xq[p], zb0p[g]);
#pragma unroll
                for (int m = 0; m < 4; m++)
                    acc = ffma2(wh0p[g][m], h0p[p][m], acc);
                float2 u = unpack2(acc);
                z[g] = u.x + u.y;
            }
            float ig = sigm(z[0]);
            float fg = sigm(z[1]);
            float gg = tanh_f(z[2]);
            float og = sigm(z[3]);
            c0[p] = fmaf(fg, c0[p], ig * gg);
            h0s[p][ql][j] = og * tanh_f(c0[p]);
        }
        __syncwarp();
#pragma unroll
        for (int p = 0; p < 4; p++) {
            const ulonglong2* row = (const ulonglong2*)&h0s[p][ql][0];
            ulonglong2 va = row[0], vb = row[1];
            h0p[p][0] = va.x; h0p[p][1] = va.y;
            h0p[p][2] = vb.x; h0p[p][3] = vb.y;
        }

        // ---- Layer 1 ----
#pragma unroll
        for (int p = 0; p < 4; p++) {
            float z[4];
#pragma unroll
            for (int g = 0; g < 4; g++) {
                u64 acc = ffma2(wi1p[g][0], h0p[p][0], zb1p[g]);
#pragma unroll
                for (int m = 1; m < 4; m++)
                    acc = ffma2(wi1p[g][m], h0p[p][m], acc);
#pragma unroll
                for (int m = 0; m < 4; m++)
                    acc = ffma2(wh1p[g][m], h1p[p][m], acc);
                float2 u = unpack2(acc);
                z[g] = u.x + u.y;
            }
            float ig = sigm(z[0]);
            float fg = sigm(z[1]);
            float gg = tanh_f(z[2]);
            float og = sigm(z[3]);
            c1[p] = fmaf(fg, c1[p], ig * gg);
            h1s[p][ql][j] = og * tanh_f(c1[p]);
        }
        __syncwarp();
#pragma unroll
        for (int p = 0; p < 4; p++) {
            const ulonglong2* row = (const ulonglong2*)&h1s[p][ql][0];
            ulonglong2 va = row[0], vb = row[1];
            h1p[p][0] = va.x; h1p[p][1] = va.y;
            h1p[p][2] = vb.x; h1p[p][3] = vb.y;
        }

        xa = na; xb = nb; xp = xn;
    }

    // ---- FC: out[b] = fc_w . h1_last + fc_b (lane j==0 writes 4) ----
    if (valid && j == 0) {
        float fw[8];
#pragma unroll
        for (int k = 0; k < 8; k++) fw[k] = __ldg(&fc_w[k]);
        float fb = __ldg(&fc_b[0]);
        float4 o;
        float* op = &o.x;
#pragma unroll
        for (int p = 0; p < 4; p++) {
            float acc = fb;
#pragma unroll
            for (int m = 0; m < 4; m++) {
                float2 u = unpack2(h1p[p][m]);
                acc = fmaf(fw[2 * m], u.x, acc);
                acc = fmaf(fw[2 * m + 1], u.y, acc);
            }
            op[p] = acc;
        }
        *(float4*)&out[4 * q] = o;
    }
}

extern "C" void kernel_launch(void* const* d_in, const int* in_sizes, int n_in,
                              void* d_out, int out_size)
{
    const float* x      = (const float*)d_in[0];
    const float* w_ih0  = (const float*)d_in[1];
    const float* w_hh0  = (const float*)d_in[2];
    const float* b_ih0  = (const float*)d_in[3];
    const float* b_hh0  = (const float*)d_in[4];
    const float* w_ih1  = (const float*)d_in[5];
    const float* w_hh1  = (const float*)d_in[6];
    const float* b_ih1  = (const float*)d_in[7];
    const float* b_hh1  = (const float*)d_in[8];
    const float* fc_w   = (const float*)d_in[9];
    const float* fc_b   = (const float*)d_in[10];
    float* out = (float*)d_out;

    int B = out_size;                 // [B, 1]
    int T = in_sizes[0] / (2 * B);    // x: [T, B, 2]

    int threads = 32;
    int total   = (B / 4) * 8;        // 8 lanes per element quad
    int blocks  = (total + threads - 1) / threads;
    lstm2_fc_kernel<<<blocks, threads>>>(x, w_ih0, w_hh0, b_ih0, b_hh0,
                                         w_ih1, w_hh1, b_ih1, b_hh1,
                                         fc_w, fc_b, out, T, B);
}

// round 6
// speedup vs baseline: 1.9754x; 1.4856x over previous
#include <cuda_runtime.h>

// 2-layer LSTM (H=8, IN=2) + FC(8->1), T=1024, B=16384.
// 8 lanes per batch element, 4 elements per thread, fma.rn.f32x2 matvecs,
// smem h-broadcast, and single-MUFU activations via tanh.approx.f32:
// sigmoid gates use half-prescaled weights so sigm(z)=0.5*tanh(z/2)+0.5.

using u64 = unsigned long long;

__device__ __forceinline__ u64 pack2(float lo, float hi) {
    u64 r; asm("mov.b64 %0, {%1, %2};" : "=l"(r) : "f"(lo), "f"(hi)); return r;
}
__device__ __forceinline__ float2 unpack2(u64 v) {
    float2 f; asm("mov.b64 {%0, %1}, %2;" : "=f"(f.x), "=f"(f.y) : "l"(v)); return f;
}
__device__ __forceinline__ u64 ffma2(u64 a, u64 b, u64 c) {
    u64 d; asm("fma.rn.f32x2 %0, %1, %2, %3;" : "=l"(d) : "l"(a), "l"(b), "l"(c)); return d;
}
__device__ __forceinline__ float tanh_a(float x) {
    float y; asm("tanh.approx.f32 %0, %1;" : "=f"(y) : "f"(x)); return y;
}

__global__ void __launch_bounds__(32)
lstm2_fc_kernel(const float* __restrict__ x,
                const float* __restrict__ w_ih0, const float* __restrict__ w_hh0,
                const float* __restrict__ b_ih0, const float* __restrict__ b_hh0,
                const float* __restrict__ w_ih1, const float* __restrict__ w_hh1,
                const float* __restrict__ b_ih1, const float* __restrict__ b_hh1,
                const float* __restrict__ fc_w, const float* __restrict__ fc_b,
                float* __restrict__ out, int T, int B)
{
    __shared__ alignas(16) float h0s[4][4][8];
    __shared__ alignas(16) float h1s[4][4][8];

    int lane  = threadIdx.x;
    int ql    = lane >> 3;         // quad slot within warp (0..3)
    int j     = lane & 7;          // hidden unit owned by this lane
    int tid   = blockIdx.x * 32 + lane;
    int q     = tid >> 3;          // global quad: elements 4q..4q+3
    int quadB = B >> 2;
    bool valid = (q < quadB);
    if (!valid) q = quadB - 1;

    // ---- Per-lane weights; sigmoid-gate rows (i,f,o) prescaled by 0.5 ----
    // Gate order: i=0, f=1, g=2(tanh), o=3.
    u64 wi0p[4], wh0p[4][4], wi1p[4][4], wh1p[4][4], zb0p[4], zb1p[4];
#pragma unroll
    for (int g = 0; g < 4; g++) {
        float sc = (g == 2) ? 1.0f : 0.5f;
        int r = g * 8 + j;
        wi0p[g] = pack2(sc * __ldg(&w_ih0[r * 2 + 0]), sc * __ldg(&w_ih0[r * 2 + 1]));
#pragma unroll
        for (int m = 0; m < 4; m++) {
            wh0p[g][m] = pack2(sc * __ldg(&w_hh0[r * 8 + 2 * m]), sc * __ldg(&w_hh0[r * 8 + 2 * m + 1]));
            wi1p[g][m] = pack2(sc * __ldg(&w_ih1[r * 8 + 2 * m]), sc * __ldg(&w_ih1[r * 8 + 2 * m + 1]));
            wh1p[g][m] = pack2(sc * __ldg(&w_hh1[r * 8 + 2 * m]), sc * __ldg(&w_hh1[r * 8 + 2 * m + 1]));
        }
        float zb0 = sc * (__ldg(&b_ih0[r]) + __ldg(&b_hh0[r]));
        float zb1 = sc * (__ldg(&b_ih1[r]) + __ldg(&b_hh1[r]));
        zb0p[g] = pack2(zb0, 0.0f);
        zb1p[g] = pack2(zb1, 0.0f);
    }

    // ---- State ----
    u64 h0p[4][4], h1p[4][4];
    float c0[4], c1[4];
    u64 zero2 = pack2(0.0f, 0.0f);
#pragma unroll
    for (int p = 0; p < 4; p++) {
        c0[p] = 0.0f; c1[p] = 0.0f;
#pragma unroll
        for (int m = 0; m < 4; m++) { h0p[p][m] = zero2; h1p[p][m] = zero2; }
    }

    int strideT = B >> 1;                       // ulonglong2 per timestep row
    const ulonglong2* xp = (const ulonglong2*)x + 2 * q;
    ulonglong2 xa = __ldg(xp);
    ulonglong2 xb = __ldg(xp + 1);

#pragma unroll 1
    for (int t = 0; t < T; t++) {
        const ulonglong2* xn = xp + ((t + 1 < T) ? strideT : 0);
        ulonglong2 na = __ldg(xn);
        ulonglong2 nb = __ldg(xn + 1);

        u64 xq[4] = { xa.x, xa.y, xb.x, xb.y };

        // ---- Layer 0 ----
#pragma unroll
        for (int p = 0; p < 4; p++) {
            float z[4];
#pragma unroll
            for (int g = 0; g < 4; g++) {
                u64 acc = ffma2(wi0p[g], xq[p], zb0p[g]);
#pragma unroll
                for (int m = 0; m < 4; m++)
                    acc = ffma2(wh0p[g][m], h0p[p][m], acc);
                float2 u = unpack2(acc);
                z[g] = u.x + u.y;
            }
            float ig = fmaf(tanh_a(z[0]), 0.5f, 0.5f);
            float fg = fmaf(tanh_a(z[1]), 0.5f, 0.5f);
            float gg = tanh_a(z[2]);
            float og = fmaf(tanh_a(z[3]), 0.5f, 0.5f);
            c0[p] = fmaf(fg, c0[p], ig * gg);
            h0s[p][ql][j] = og * tanh_a(c0[p]);
        }
        __syncwarp();
#pragma unroll
        for (int p = 0; p < 4; p++) {
            const ulonglong2* row = (const ulonglong2*)&h0s[p][ql][0];
            ulonglong2 va = row[0], vb = row[1];
            h0p[p][0] = va.x; h0p[p][1] = va.y;
            h0p[p][2] = vb.x; h0p[p][3] = vb.y;
        }

        // ---- Layer 1 ----
#pragma unroll
        for (int p = 0; p < 4; p++) {
            float z[4];
#pragma unroll
            for (int g = 0; g < 4; g++) {
                u64 acc = ffma2(wi1p[g][0], h0p[p][0], zb1p[g]);
#pragma unroll
                for (int m = 1; m < 4; m++)
                    acc = ffma2(wi1p[g][m], h0p[p][m], acc);
#pragma unroll
                for (int m = 0; m < 4; m++)
                    acc = ffma2(wh1p[g][m], h1p[p][m], acc);
                float2 u = unpack2(acc);
                z[g] = u.x + u.y;
            }
            float ig = fmaf(tanh_a(z[0]), 0.5f, 0.5f);
            float fg = fmaf(tanh_a(z[1]), 0.5f, 0.5f);
            float gg = tanh_a(z[2]);
            float og = fmaf(tanh_a(z[3]), 0.5f, 0.5f);
            c1[p] = fmaf(fg, c1[p], ig * gg);
            h1s[p][ql][j] = og * tanh_a(c1[p]);
        }
        __syncwarp();
#pragma unroll
        for (int p = 0; p < 4; p++) {
            const ulonglong2* row = (const ulonglong2*)&h1s[p][ql][0];
            ulonglong2 va = row[0], vb = row[1];
            h1p[p][0] = va.x; h1p[p][1] = va.y;
            h1p[p][2] = vb.x; h1p[p][3] = vb.y;
        }

        xa = na; xb = nb; xp = xn;
    }

    // ---- FC: out[b] = fc_w . h1_last + fc_b (lane j==0 writes 4) ----
    if (valid && j == 0) {
        float fw[8];
#pragma unroll
        for (int k = 0; k < 8; k++) fw[k] = __ldg(&fc_w[k]);
        float fb = __ldg(&fc_b[0]);
        float4 o;
        float* op = &o.x;
#pragma unroll
        for (int p = 0; p < 4; p++) {
            float acc = fb;
#pragma unroll
            for (int m = 0; m < 4; m++) {
                float2 u = unpack2(h1p[p][m]);
                acc = fmaf(fw[2 * m], u.x, acc);
                acc = fmaf(fw[2 * m + 1], u.y, acc);
            }
            op[p] = acc;
        }
        *(float4*)&out[4 * q] = o;
    }
}

extern "C" void kernel_launch(void* const* d_in, const int* in_sizes, int n_in,
                              void* d_out, int out_size)
{
    const float* x      = (const float*)d_in[0];
    const float* w_ih0  = (const float*)d_in[1];
    const float* w_hh0  = (const float*)d_in[2];
    const float* b_ih0  = (const float*)d_in[3];
    const float* b_hh0  = (const float*)d_in[4];
    const float* w_ih1  = (const float*)d_in[5];
    const float* w_hh1  = (const float*)d_in[6];
    const float* b_ih1  = (const float*)d_in[7];
    const float* b_hh1  = (const float*)d_in[8];
    const float* fc_w   = (const float*)d_in[9];
    const float* fc_b   = (const float*)d_in[10];
    float* out = (float*)d_out;

    int B = out_size;                 // [B, 1]
    int T = in_sizes[0] / (2 * B);    // x: [T, B, 2]

    int threads = 32;
    int total   = (B / 4) * 8;        // 8 lanes per element quad
    int blocks  = (total + threads - 1) / threads;
    lstm2_fc_kernel<<<blocks, threads>>>(x, w_ih0, w_hh0, b_ih0, b_hh0,
                                         w_ih1, w_hh1, b_ih1, b_hh1,
                                         fc_w, fc_b, out, T, B);
}